// round 2
// baseline (speedup 1.0000x reference)
#include <cuda_runtime.h>

#define N_SAMPLES 32768
#define N_ITERS   16
#define KLEN      256
#define N_FRAMES  512
#define N_ATOMS   256
#define THREADS   1024
#define STEP      (N_SAMPLES / N_FRAMES)   // 64
#define PER_THREAD (N_SAMPLES / THREADS)   // 32

__global__ __launch_bounds__(THREADS, 1)
void Model_67817533604348_kernel(const float* __restrict__ atom_sel,   // [16,256]
                                 const float* __restrict__ amps,       // [16,1]
                                 const float* __restrict__ sched,      // [16,512]
                                 const float* __restrict__ d,          // [256,256]
                                 float* __restrict__ out)              // [32768]
{
    __shared__ float s_atoms[N_ITERS][KLEN];   // amp-scaled selected rows of d
    __shared__ int   s_aidx[N_ITERS];
    __shared__ int   s_pos[N_ITERS];
    __shared__ float s_red[32];
    __shared__ float s_scale;

    const int tid  = threadIdx.x;
    const int wid  = tid >> 5;
    const int lane = tid & 31;

    // ---------------- Phase 1: per-iter argmaxes (one warp each) ----------------
    if (wid < N_ITERS) {
        // argmax over atom_selection[wid, 0:256]  (softmax is monotone -> argmax of logits)
        const float* row = atom_sel + wid * N_ATOMS;
        float bv = -3.402823466e38f;
        int   bi = 0x7fffffff;
        #pragma unroll
        for (int c = lane; c < N_ATOMS; c += 32) {
            float v = row[c];
            if (v > bv) { bv = v; bi = c; }
        }
        #pragma unroll
        for (int o = 16; o > 0; o >>= 1) {
            float ov = __shfl_down_sync(0xffffffffu, bv, o);
            int   oi = __shfl_down_sync(0xffffffffu, bi, o);
            if (ov > bv || (ov == bv && oi < bi)) { bv = ov; bi = oi; }
        }
        if (lane == 0) s_aidx[wid] = bi;
    } else {
        // argmax over sched_params[i, 0:512] -> impulse position i*64
        const int i = wid - N_ITERS;
        const float* row = sched + i * N_FRAMES;
        float bv = -3.402823466e38f;
        int   bi = 0x7fffffff;
        #pragma unroll
        for (int c = lane; c < N_FRAMES; c += 32) {
            float v = row[c];
            if (v > bv) { bv = v; bi = c; }
        }
        #pragma unroll
        for (int o = 16; o > 0; o >>= 1) {
            float ov = __shfl_down_sync(0xffffffffu, bv, o);
            int   oi = __shfl_down_sync(0xffffffffu, bi, o);
            if (ov > bv || (ov == bv && oi < bi)) { bv = ov; bi = oi; }
        }
        if (lane == 0) s_pos[i] = bi * STEP;
    }
    __syncthreads();

    // ---------------- Phase 1b: stage amp-scaled atoms into smem ----------------
    // 16*256 = 4096 floats, 1024 threads -> 4 each
    #pragma unroll
    for (int e = tid; e < N_ITERS * KLEN; e += THREADS) {
        const int i = e >> 8;        // iter
        const int k = e & (KLEN - 1);
        s_atoms[i][k] = amps[i] * d[s_aidx[i] * KLEN + k];
    }
    __syncthreads();

    // ---------------- Phase 2: accumulate shifted atoms ----------------
    // Thread tid owns samples n = tid + j*1024 (strided): conflict-free smem,
    // coalesced gmem. Atom window (256) < stride (1024) -> <=1 hit per iter.
    float acc[PER_THREAD];
    #pragma unroll
    for (int j = 0; j < PER_THREAD; j++) acc[j] = 0.0f;

    #pragma unroll
    for (int i = 0; i < N_ITERS; i++) {
        const int p = s_pos[i];
        const float* __restrict__ atom = s_atoms[i];
        int off = tid - p;
        #pragma unroll
        for (int j = 0; j < PER_THREAD; j++) {
            if ((unsigned)off < (unsigned)KLEN) acc[j] += atom[off];
            off += THREADS;
        }
    }

    // ---------------- Phase 3: block max-abs reduce ----------------
    float mx = 0.0f;
    #pragma unroll
    for (int j = 0; j < PER_THREAD; j++) mx = fmaxf(mx, fabsf(acc[j]));
    #pragma unroll
    for (int o = 16; o > 0; o >>= 1)
        mx = fmaxf(mx, __shfl_xor_sync(0xffffffffu, mx, o));
    if (lane == 0) s_red[wid] = mx;
    __syncthreads();
    if (wid == 0) {
        float m = s_red[lane];
        #pragma unroll
        for (int o = 16; o > 0; o >>= 1)
            m = fmaxf(m, __shfl_xor_sync(0xffffffffu, m, o));
        if (lane == 0) s_scale = 1.0f / (m + 1e-8f);
    }
    __syncthreads();

    // ---------------- Phase 4: normalized coalesced store ----------------
    const float scale = s_scale;
    #pragma unroll
    for (int j = 0; j < PER_THREAD; j++)
        out[tid + j * THREADS] = acc[j] * scale;
}

extern "C" void kernel_launch(void* const* d_in, const int* in_sizes, int n_in,
                              void* d_out, int out_size) {
    // metadata order: x (unused), atom_selection, amps, sched_params, d
    const float* atom_sel = (const float*)d_in[1];
    const float* amps     = (const float*)d_in[2];
    const float* sched    = (const float*)d_in[3];
    const float* d        = (const float*)d_in[4];
    float* out            = (float*)d_out;

    Model_67817533604348_kernel<<<1, THREADS>>>(atom_sel, amps, sched, d, out);
}

// round 3
// speedup vs baseline: 1.6347x; 1.6347x over previous
#include <cuda_runtime.h>

#define N_SAMPLES 32768
#define N_ITERS   16
#define KLEN      256
#define N_FRAMES  512
#define N_ATOMS   256
#define THREADS   1024
#define STEP      (N_SAMPLES / N_FRAMES)   // 64

// dynamic smem: the full 32768-float signal (128 KB)
extern __shared__ float sig[];

__global__ __launch_bounds__(THREADS, 1)
void Model_67817533604348_kernel(const float* __restrict__ atom_sel,   // [16,256]
                                 const float* __restrict__ amps,       // [16,1]
                                 const float* __restrict__ sched,      // [16,512]
                                 const float* __restrict__ d,          // [256,256]
                                 float* __restrict__ out)              // [32768]
{
    __shared__ int   s_aidx[N_ITERS];
    __shared__ int   s_pos[N_ITERS];
    __shared__ float s_red[32];
    __shared__ float s_scale;

    const int tid  = threadIdx.x;
    const int wid  = tid >> 5;
    const int lane = tid & 31;

    // ---------------- Phase 0: zero the signal (float4, conflict-free) ----------
    float4* sig4 = reinterpret_cast<float4*>(sig);
    #pragma unroll
    for (int j = 0; j < 8; j++)
        sig4[tid + j * THREADS] = make_float4(0.f, 0.f, 0.f, 0.f);

    // ---------------- Phase 1: per-iter argmaxes (one warp each) ----------------
    // softmax is monotone -> argmax of raw logits; soft_dirac forward is exact one-hot
    if (wid < N_ITERS) {
        const float* row = atom_sel + wid * N_ATOMS;
        float bv = -3.402823466e38f;
        int   bi = 0x7fffffff;
        #pragma unroll
        for (int c = lane; c < N_ATOMS; c += 32) {
            float v = row[c];
            if (v > bv) { bv = v; bi = c; }
        }
        #pragma unroll
        for (int o = 16; o > 0; o >>= 1) {
            float ov = __shfl_down_sync(0xffffffffu, bv, o);
            int   oi = __shfl_down_sync(0xffffffffu, bi, o);
            if (ov > bv || (ov == bv && oi < bi)) { bv = ov; bi = oi; }
        }
        if (lane == 0) s_aidx[wid] = bi;
    } else {
        const int i = wid - N_ITERS;
        const float* row = sched + i * N_FRAMES;
        float bv = -3.402823466e38f;
        int   bi = 0x7fffffff;
        #pragma unroll
        for (int c = lane; c < N_FRAMES; c += 32) {
            float v = row[c];
            if (v > bv) { bv = v; bi = c; }
        }
        #pragma unroll
        for (int o = 16; o > 0; o >>= 1) {
            float ov = __shfl_down_sync(0xffffffffu, bv, o);
            int   oi = __shfl_down_sync(0xffffffffu, bi, o);
            if (ov > bv || (ov == bv && oi < bi)) { bv = ov; bi = oi; }
        }
        if (lane == 0) s_pos[i] = bi * STEP;   // impulse sample position
    }
    __syncthreads();   // zeroing + argmax results visible

    // ---------------- Phase 2: sparse scatter-add of shifted atoms --------------
    // 16 iters x 256 taps = 4096 tasks; thread owns 4 consecutive taps of one iter.
    const int e0 = tid * 4;
    const int it = e0 >> 8;          // iter index (4 | 256, so constant per thread)
    const int k0 = e0 & (KLEN - 1);  // first tap
    const float  amp = amps[it];
    const float4 dv  = *reinterpret_cast<const float4*>(d + s_aidx[it] * KLEN + k0);
    const int s0 = s_pos[it] + k0;   // first sample (window may truncate at 32768)

    float vals[4] = { amp * dv.x, amp * dv.y, amp * dv.z, amp * dv.w };
    #pragma unroll
    for (int q = 0; q < 4; q++) {
        const int s = s0 + q;
        if (s < N_SAMPLES) atomicAdd(&sig[s], vals[q]);
    }
    __syncthreads();

    // ---------------- Phase 3: max-abs over window samples only -----------------
    // Samples outside the 16 windows are exactly 0, and max|x| >= 0 always.
    float mx = 0.0f;
    #pragma unroll
    for (int q = 0; q < 4; q++) {
        const int s = s0 + q;
        if (s < N_SAMPLES) mx = fmaxf(mx, fabsf(sig[s]));
    }
    #pragma unroll
    for (int o = 16; o > 0; o >>= 1)
        mx = fmaxf(mx, __shfl_xor_sync(0xffffffffu, mx, o));
    if (lane == 0) s_red[wid] = mx;
    __syncthreads();
    if (wid == 0) {
        float m = s_red[lane];
        #pragma unroll
        for (int o = 16; o > 0; o >>= 1)
            m = fmaxf(m, __shfl_xor_sync(0xffffffffu, m, o));
        if (lane == 0) s_scale = 1.0f / (m + 1e-8f);
    }
    __syncthreads();

    // ---------------- Phase 4: normalized coalesced vector store ----------------
    const float scale = s_scale;
    float4* out4 = reinterpret_cast<float4*>(out);
    #pragma unroll
    for (int j = 0; j < 8; j++) {
        float4 v = sig4[tid + j * THREADS];
        v.x *= scale; v.y *= scale; v.z *= scale; v.w *= scale;
        out4[tid + j * THREADS] = v;
    }
}

extern "C" void kernel_launch(void* const* d_in, const int* in_sizes, int n_in,
                              void* d_out, int out_size) {
    // metadata order: x (unused), atom_selection, amps, sched_params, d
    const float* atom_sel = (const float*)d_in[1];
    const float* amps     = (const float*)d_in[2];
    const float* sched    = (const float*)d_in[3];
    const float* d        = (const float*)d_in[4];
    float* out            = (float*)d_out;

    const int smem = N_SAMPLES * (int)sizeof(float);  // 128 KB
    cudaFuncSetAttribute(Model_67817533604348_kernel,
                         cudaFuncAttributeMaxDynamicSharedMemorySize, smem);
    Model_67817533604348_kernel<<<1, THREADS, smem>>>(atom_sel, amps, sched, d, out);
}